// round 10
// baseline (speedup 1.0000x reference)
#include <cuda_runtime.h>
#include <cuda_fp16.h>
#include <stdint.h>
#include <math.h>

#define HDIM    4096
#define NEXP    256
#define KC      32
#define NCHUNK  128
#define MTILE   64
#define TOPK    8
#define NSTAGE  4

#define B_SP        16384            // one B split tile: 256 rows x 64B
#define B_STAGE     32768            // h + m splits
#define SM_BASE     1024
#define SMEM_BYTES  (SM_BASE + NSTAGE*B_STAGE)   // 132096
#define LSTR 260

// mbarrier offsets (within smem, before SM_BASE)
#define OFF_FULL(s)  (64 + (s)*16)
#define OFF_EMPTY(s) (72 + (s)*16)

// Pre-split, pre-swizzled W (fp16 h + m*4096): [chunk32][2 splits][16KB]
__device__ __align__(128) uint8_t g_wt[(size_t)NCHUNK * B_STAGE];

__device__ __forceinline__ uint32_t smem_u32(const void* p) {
    uint32_t a;
    asm("{ .reg .u64 t; cvta.to.shared.u64 t, %1; cvt.u32.u64 %0, t; }" : "=r"(a) : "l"(p));
    return a;
}
__device__ __forceinline__ uint32_t swz64(uint32_t o) { return o ^ ((o >> 3) & 0x30); }

__device__ __forceinline__ uint32_t packh(float lo, float hi) {
    __half2 h = __floats2half2_rn(lo, hi);   // .x = lo (low 16) = even k elem
    return *(uint32_t*)&h;
}
// x = h + m*2^-12, m kept fp16-normal; residual <= ~2^-24 |x|
__device__ __forceinline__ void split2(float x0, float x1, uint32_t& h, uint32_t& m) {
    h = packh(x0, x1);
    __half2 hh = *(__half2*)&h;
    float h0 = __low2float(hh), h1 = __high2float(hh);
    m = packh((x0 - h0) * 4096.0f, (x1 - h1) * 4096.0f);
}

__device__ __forceinline__ void mbar_init(uint32_t a, uint32_t c) {
    asm volatile("mbarrier.init.shared.b64 [%0], %1;" :: "r"(a), "r"(c) : "memory");
}
__device__ __forceinline__ void mbar_arrive(uint32_t a) {
    asm volatile("mbarrier.arrive.shared.b64 _, [%0];" :: "r"(a) : "memory");
}
__device__ __forceinline__ void mbar_expect_tx(uint32_t a, uint32_t b) {
    asm volatile("mbarrier.arrive.expect_tx.shared.b64 _, [%0], %1;" :: "r"(a), "r"(b) : "memory");
}
__device__ __forceinline__ void mbar_wait(uint32_t a, uint32_t ph) {
    uint32_t done;
    asm volatile("{\n\t.reg .pred p;\n\t"
                 "mbarrier.try_wait.parity.acquire.cta.shared::cta.b64 p, [%1], %2;\n\t"
                 "selp.b32 %0,1,0,p;\n\t}" : "=r"(done) : "r"(a), "r"(ph) : "memory");
    if (!done) {
        asm volatile("{\n\t.reg .pred P;\n"
                     "W0_%=:\n\t"
                     "mbarrier.try_wait.parity.acquire.cta.shared::cta.b64 P, [%0], %1, 0x989680;\n\t"
                     "@P bra W1_%=;\n\t"
                     "bra W0_%=;\n"
                     "W1_%=:\n\t}" :: "r"(a), "r"(ph) : "memory");
    }
}
__device__ __forceinline__ void bulk_cp(uint32_t dst, const void* src, uint32_t bytes, uint32_t mbar) {
    asm volatile("cp.async.bulk.shared::cluster.global.mbarrier::complete_tx::bytes "
                 "[%0], [%1], %2, [%3];"
                 :: "r"(dst), "l"(src), "r"(bytes), "r"(mbar) : "memory");
}

#define LDSM4(r, addr)                                                           \
    asm volatile("ldmatrix.sync.aligned.m8n8.x4.shared.b16 {%0,%1,%2,%3}, [%4];" \
        : "=r"((r)[0]), "=r"((r)[1]), "=r"((r)[2]), "=r"((r)[3]) : "r"(addr))

#define MMA_ACC(c, a, b0v, b1v)                                                  \
    asm volatile("mma.sync.aligned.m16n8k16.row.col.f32.f16.f16.f32 "            \
        "{%0,%1,%2,%3}, {%4,%5,%6,%7}, {%8,%9}, {%0,%1,%2,%3};"                  \
        : "+f"((c)[0]), "+f"((c)[1]), "+f"((c)[2]), "+f"((c)[3])                 \
        : "r"((a)[0]), "r"((a)[1]), "r"((a)[2]), "r"((a)[3]), "r"(b0v), "r"(b1v))

#define MMA_NEW(c, a, b0v, b1v)                                                  \
    asm volatile("mma.sync.aligned.m16n8k16.row.col.f32.f16.f16.f32 "            \
        "{%0,%1,%2,%3}, {%4,%5,%6,%7}, {%8,%9}, {%10,%10,%10,%10};"              \
        : "=f"((c)[0]), "=f"((c)[1]), "=f"((c)[2]), "=f"((c)[3])                 \
        : "r"((a)[0]), "r"((a)[1]), "r"((a)[2]), "r"((a)[3]), "r"(b0v), "r"(b1v),\
          "f"(0.0f))

// ---------------- W pre-split kernel: grid=128 k32-chunks, 256 thr = experts ---
__global__ void __launch_bounds__(256) wprep_kernel(const float* __restrict__ w) {
    const int c = blockIdx.x;
    const int e = threadIdx.x;
    const float4* src = (const float4*)(w + (size_t)e * HDIM + c * KC);
    float xv[32];
    #pragma unroll
    for (int i = 0; i < 8; i++) {
        float4 f = src[i];
        xv[i*4+0]=f.x; xv[i*4+1]=f.y; xv[i*4+2]=f.z; xv[i*4+3]=f.w;
    }
    uint32_t hh[16], mm_[16];
    #pragma unroll
    for (int j = 0; j < 16; j++) split2(xv[2*j], xv[2*j+1], hh[j], mm_[j]);
    uint8_t* base = g_wt + (size_t)c * B_STAGE;
    #pragma unroll
    for (int b = 0; b < 4; b++) {
        uint32_t so = swz64((uint32_t)e * 64 + b * 16);
        *(uint4*)(base + 0*B_SP + so) = make_uint4(hh[4*b],hh[4*b+1],hh[4*b+2],hh[4*b+3]);
        *(uint4*)(base + 1*B_SP + so) = make_uint4(mm_[4*b],mm_[4*b+1],mm_[4*b+2],mm_[4*b+3]);
    }
}

// ---------------- main kernel: grid = T/64, 256 threads (8 warps 2Mx4N) --------
__global__ void __launch_bounds__(256, 1)
moe_gate_mma(const float* __restrict__ x, float* __restrict__ out, int T) {
    extern __shared__ __align__(1024) uint8_t smem[];
    const uint32_t sbase = smem_u32(smem);
    const int tid  = threadIdx.x;
    const int wid  = tid >> 5;
    const int lane = tid & 31;
    const int row_base = blockIdx.x * MTILE;

    if (tid == 0) {
        #pragma unroll
        for (int s = 0; s < NSTAGE; s++) {
            mbar_init(sbase + OFF_FULL(s), 1);
            mbar_init(sbase + OFF_EMPTY(s), 8);
        }
    }

    // warp tile: 32M x 64N  (8 warps = 2M x 4N)
    const int wm = wid & 1, wn = wid >> 1;
    const int m0 = wm * 32, n0 = wn * 64;

    // A fragment source pointer: thread covers rows (m0 + lane/4) (+8,+16,+24),
    // k columns (lane%4)*2 (+1, +8, +9) per k16 step.
    const float* rpA = x + (size_t)(row_base + m0 + (lane >> 2)) * HDIM + (lane & 3) * 2;

    // swizzled ldmatrix offsets for B (rows = experts, 64B rows, SW64)
    uint32_t boff[2][4];
    {
        uint32_t b_n  = (uint32_t)(n0 + (lane & 7) + ((lane >> 4) & 1) * 8);
        uint32_t b_kh = (uint32_t)((lane >> 3) & 1) * 16;
        #pragma unroll
        for (int ks = 0; ks < 2; ks++)
            #pragma unroll
            for (int nb = 0; nb < 4; nb++)
                boff[ks][nb] = swz64((b_n + nb*16) * 64 + ks*32 + b_kh);
    }

    float master[2][8][4];   // fp32-RN sum of hh products
    float winc[2][8][4];     // hm+mh chained window (x4096)
    #pragma unroll
    for (int mi = 0; mi < 2; mi++)
        #pragma unroll
        for (int j = 0; j < 8; j++)
            #pragma unroll
            for (int q = 0; q < 4; q++)
                { master[mi][j][q] = 0.0f; winc[mi][j][q] = 0.0f; }

    __syncthreads();   // mbarriers visible

    // producer prologue: fill stages 0..2
    if (tid == 0) {
        #pragma unroll
        for (int j = 0; j < 3; j++) {
            mbar_expect_tx(sbase + OFF_FULL(j), B_STAGE);
            bulk_cp(sbase + SM_BASE + j * B_STAGE, g_wt + (size_t)j * B_STAGE,
                    B_STAGE, sbase + OFF_FULL(j));
        }
    }

    for (int c = 0; c < NCHUNK; c++) {
        const int s = c & 3;

        // producer: keep 3 chunks of runway
        if (tid == 0) {
            const int j = c + 3;
            if (j < NCHUNK) {
                const int js = j & 3;
                if (j >= NSTAGE)
                    mbar_wait(sbase + OFF_EMPTY(js), ((j - NSTAGE) >> 2) & 1);
                mbar_expect_tx(sbase + OFF_FULL(js), B_STAGE);
                bulk_cp(sbase + SM_BASE + js * B_STAGE, g_wt + (size_t)j * B_STAGE,
                        B_STAGE, sbase + OFF_FULL(js));
            }
        }

        // consumer: wait B stage ready
        mbar_wait(sbase + OFF_FULL(s), (c >> 2) & 1);
        const uint32_t Bb = sbase + SM_BASE + (uint32_t)s * B_STAGE;
        const int kbase = c * KC;

        #pragma unroll
        for (int ks = 0; ks < 2; ks++) {
            // B fragments from smem
            uint32_t Bh[4][4], Bm[4][4];
            #pragma unroll
            for (int nb = 0; nb < 4; nb++) LDSM4(Bh[nb], Bb + boff[ks][nb]);
            #pragma unroll
            for (int nb = 0; nb < 4; nb++) LDSM4(Bm[nb], Bb + B_SP + boff[ks][nb]);

            // A fragments straight from global + register split
            uint32_t Ah[2][4], Am[2][4];
            #pragma unroll
            for (int mi = 0; mi < 2; mi++)
                #pragma unroll
                for (int idx = 0; idx < 4; idx++) {
                    size_t off = (size_t)(mi*16 + (idx & 1)*8) * HDIM
                               + kbase + ks*16 + (idx >> 1)*8;
                    float2 v = *(const float2*)(rpA + off);
                    split2(v.x, v.y, Ah[mi][idx], Am[mi][idx]);
                }

            // hh: fresh C per MMA, immediate fp32-RN drain
            #pragma unroll
            for (int mi = 0; mi < 2; mi++) {
                float wh[8][4];
                #pragma unroll
                for (int nb = 0; nb < 4; nb++) {
                    MMA_NEW(wh[nb*2+0], Ah[mi], Bh[nb][0], Bh[nb][1]);
                    MMA_NEW(wh[nb*2+1], Ah[mi], Bh[nb][2], Bh[nb][3]);
                }
                #pragma unroll
                for (int j = 0; j < 8; j++)
                    #pragma unroll
                    for (int q = 0; q < 4; q++)
                        master[mi][j][q] += wh[j][q];
            }
            // mh + hm into chained correction window
            #pragma unroll
            for (int mi = 0; mi < 2; mi++)
                #pragma unroll
                for (int nb = 0; nb < 4; nb++) {
                    MMA_ACC(winc[mi][nb*2+0], Am[mi], Bh[nb][0], Bh[nb][1]);
                    MMA_ACC(winc[mi][nb*2+1], Am[mi], Bh[nb][2], Bh[nb][3]);
                }
            #pragma unroll
            for (int mi = 0; mi < 2; mi++)
                #pragma unroll
                for (int nb = 0; nb < 4; nb++) {
                    MMA_ACC(winc[mi][nb*2+0], Ah[mi], Bm[nb][0], Bm[nb][1]);
                    MMA_ACC(winc[mi][nb*2+1], Ah[mi], Bm[nb][2], Bm[nb][3]);
                }
        }

        // release stage (one arrive per warp; empty count = 8)
        if (lane == 0) mbar_arrive(sbase + OFF_EMPTY(s));
    }

    // combine: logits = master + winc * 2^-12
    const float CS = 1.0f / 4096.0f;
    #pragma unroll
    for (int mi = 0; mi < 2; mi++)
        #pragma unroll
        for (int j = 0; j < 8; j++)
            #pragma unroll
            for (int q = 0; q < 4; q++)
                master[mi][j][q] = fmaf(winc[mi][j][q], CS, master[mi][j][q]);

    __syncthreads();   // all warps done with B stages; smem reusable for logits

    // ---- epilogue: dump logits to smem, per-thread top-8 ----
    float* lg = (float*)(smem + SM_BASE);
    #pragma unroll
    for (int mi = 0; mi < 2; mi++)
        #pragma unroll
        for (int j = 0; j < 8; j++) {
            int r = m0 + mi*16 + (lane >> 2);
            int cc = n0 + j*8 + 2*(lane & 3);
            *(float2*)&lg[(size_t)r * LSTR + cc]       = make_float2(master[mi][j][0], master[mi][j][1]);
            *(float2*)&lg[(size_t)(r + 8) * LSTR + cc] = make_float2(master[mi][j][2], master[mi][j][3]);
        }
    __syncthreads();

    if (tid < MTILE) {
        const int row = row_base + tid;
        float tv[TOPK]; int ti[TOPK];
        #pragma unroll
        for (int t = 0; t < TOPK; t++) { tv[t] = -INFINITY; ti[t] = 0x7fffffff; }
        const float* lr = &lg[(size_t)tid * LSTR];
        for (int g = 0; g < 64; g++) {
            float4 v4 = *(const float4*)(lr + g * 4);
            float vs[4] = {v4.x, v4.y, v4.z, v4.w};
            #pragma unroll
            for (int q = 0; q < 4; q++) {
                float v = vs[q];
                if (v > tv[TOPK-1]) {
                    tv[TOPK-1] = v; ti[TOPK-1] = g*4 + q;
                    #pragma unroll
                    for (int t = TOPK-1; t > 0; t--) {
                        if (tv[t] > tv[t-1]) {
                            float fv = tv[t]; tv[t] = tv[t-1]; tv[t-1] = fv;
                            int   fi = ti[t]; ti[t] = ti[t-1]; ti[t-1] = fi;
                        }
                    }
                }
            }
        }
        // Z cancels under top-k renorm: w_t = 2.5 * exp(v_t - mx) / sum
        float e[TOPK], ssum = 0.0f;
        #pragma unroll
        for (int t = 0; t < TOPK; t++) { e[t] = expf(tv[t] - tv[0]); ssum += e[t]; }
        const float scale = 2.5f / ssum;
        const size_t base = (size_t)row * TOPK;
        const size_t wofs = (size_t)T * TOPK;
        #pragma unroll
        for (int t = 0; t < TOPK; t++) {
            out[base + t]        = (float)ti[t];
            out[wofs + base + t] = e[t] * scale;
        }
    }
}

extern "C" void kernel_launch(void* const* d_in, const int* in_sizes, int n_in,
                              void* d_out, int out_size) {
    const float* x = (const float*)d_in[0];
    const float* w = (const float*)d_in[1];
    float* out = (float*)d_out;
    int T = in_sizes[0] / HDIM;   // 16384

    cudaFuncSetAttribute(moe_gate_mma, cudaFuncAttributeMaxDynamicSharedMemorySize, SMEM_BYTES);

    wprep_kernel<<<NCHUNK, 256>>>(w);
    moe_gate_mma<<<T / MTILE, 256, SMEM_BYTES>>>(x, out, T);
}